// round 15
// baseline (speedup 1.0000x reference)
#include <cuda_runtime.h>
#include <cuda_bf16.h>
#include <cuda_fp16.h>
#include <math.h>
#include <float.h>
#include <stdint.h>

#define BB 16
#define NN 4096
#define DD 1024
#define KK 1024
#define MM (NN - KK)   // 3072

#define THR  132.0f    // safe coarse margin (validated R8/R10/R12/R13: zero flips)
#define TCUT 160.0f    // tile-candidate cut (conservative >= 2E)

// ---------------- device scratch (no allocations allowed) ----------------
__device__ int   g_kept_idx[BB * KK];
__device__ float g_kept_sc [BB * KK];
__device__ int   g_drop_idx[BB * MM];
__device__ float g_drop_sc [BB * MM];
__device__ float g_sacc    [BB * KK];
__device__ unsigned long long g_amax[BB * MM];   // packed (orderfloat<<32 | ~col)
__device__ float g_t1val[(size_t)BB * MM * 16];  // per (row, tile, n-half)
__device__ int   g_t1col[(size_t)BB * MM * 16];
__device__ float g_t2val[(size_t)BB * MM * 16];
__device__ int   g_flag2[(size_t)BB * 8 * MM];   // per-(batch,tile) row lists
__device__ int   g_nflag2[BB * 8];
__device__ int   g_assign[BB * MM];

// fp16 hi/lo split of (normalized * 256) gathered rows
__device__ __align__(16) __half g_Dh[(size_t)BB * MM * DD];
__device__ __align__(16) __half g_Dl[(size_t)BB * MM * DD];
__device__ __align__(16) __half g_Kh[(size_t)BB * KK * DD];
__device__ __align__(16) __half g_Kl[(size_t)BB * KK * DD];

// ---------------- PTX helpers ----------------
__device__ __forceinline__ uint32_t smem_u32(const void* p) {
    uint32_t a;
    asm("{ .reg .u64 t; cvta.to.shared.u64 t, %1; cvt.u32.u64 %0, t; }" : "=r"(a) : "l"(p));
    return a;
}
__device__ __forceinline__ void cp16cg(uint32_t dst, const void* src) {
    asm volatile("cp.async.cg.shared.global [%0], [%1], 16;" :: "r"(dst), "l"(src));
}
__device__ __forceinline__ void cp16ca(uint32_t dst, const void* src) {
    asm volatile("cp.async.ca.shared.global [%0], [%1], 16;" :: "r"(dst), "l"(src));
}
#define CP_COMMIT() asm volatile("cp.async.commit_group;" ::: "memory")
#define CP_WAIT1()  asm volatile("cp.async.wait_group 1;" ::: "memory")
#define CP_WAIT0()  asm volatile("cp.async.wait_group 0;" ::: "memory")

__device__ __forceinline__ void ldsm_x4(uint32_t* r, uint32_t addr) {
    asm volatile("ldmatrix.sync.aligned.m8n8.x4.shared.b16 {%0,%1,%2,%3}, [%4];"
        : "=r"(r[0]), "=r"(r[1]), "=r"(r[2]), "=r"(r[3]) : "r"(addr));
}
__device__ __forceinline__ void mma16816h(float* c, const uint32_t* a, uint32_t b0, uint32_t b1) {
    asm volatile(
        "mma.sync.aligned.m16n8k16.row.col.f32.f16.f16.f32 "
        "{%0,%1,%2,%3}, {%4,%5,%6,%7}, {%8,%9}, {%0,%1,%2,%3};"
        : "+f"(c[0]), "+f"(c[1]), "+f"(c[2]), "+f"(c[3])
        : "r"(a[0]), "r"(a[1]), "r"(a[2]), "r"(a[3]), "r"(b0), "r"(b1));
}
__device__ __forceinline__ unsigned long long shfl_xor_u64(unsigned long long x, int m) {
    uint32_t lo = (uint32_t)x, hi = (uint32_t)(x >> 32);
    lo = __shfl_xor_sync(0xffffffffu, lo, m);
    hi = __shfl_xor_sync(0xffffffffu, hi, m);
    return ((unsigned long long)hi << 32) | lo;
}

// swizzled smem offsets
// 64B rows (recheck tiles): chunk in 16B granules, chunk ^= (row>>1)&3
__device__ __forceinline__ uint32_t swz(int row, int chunk) {
    return (uint32_t)(row * 64 + ((chunk ^ ((row >> 1) & 3)) << 4));
}
// 128B rows (gemm1 tiles): classic SW128, granule chunk ^= row&7
__device__ __forceinline__ uint32_t swz128(int row, int chunk) {
    return (uint32_t)(row * 128 + ((chunk ^ (row & 7)) << 4));
}

// ---------------- block scan helper ----------------
__device__ __forceinline__ int block_excl_scan_1024(int val, int* wsum) {
    int tid = threadIdx.x;
    int lane = tid & 31, w = tid >> 5;
    __syncthreads();
    int v = val;
#pragma unroll
    for (int off = 1; off < 32; off <<= 1) {
        int n = __shfl_up_sync(0xffffffffu, v, off);
        if (lane >= off) v += n;
    }
    if (lane == 31) wsum[w] = v;
    __syncthreads();
    if (w == 0) {
        int s = wsum[lane];
#pragma unroll
        for (int off = 1; off < 32; off <<= 1) {
            int n = __shfl_up_sync(0xffffffffu, s, off);
            if (lane >= off) s += n;
        }
        wsum[lane] = s;
    }
    __syncthreads();
    int base = (w ? wsum[w - 1] : 0);
    return base + v - val;
}

// ---------------- K1: exact top-K select (value desc, index asc ties) ------
__global__ void __launch_bounds__(1024) topk_kernel(const float* __restrict__ scores,
                                                    float* __restrict__ out_idx,
                                                    float* __restrict__ out_sc,
                                                    int write_out)
{
    const int b   = blockIdx.x;
    const int tid = threadIdx.x;

    __shared__ float sh[NN];
    __shared__ int   hist[NN];
    __shared__ float tlv[1024];
    __shared__ int   tli[1024];
    __shared__ int   wsum[32];
    __shared__ int   s_t, s_C, s_nt;

    const float* sc = scores + (size_t)b * NN;
#pragma unroll
    for (int q = 0; q < 4; q++) {
        int i = tid * 4 + q;
        sh[i]   = sc[i];
        hist[i] = 0;
    }
    if (tid == 0) s_nt = 0;
    __syncthreads();

#pragma unroll
    for (int q = 0; q < 4; q++) {
        int i = tid * 4 + q;
        float s = sh[i];
        int bkt = (int)(s * (float)NN);
        bkt = max(0, min(NN - 1, bkt));
        atomicAdd(&hist[bkt], 1);
    }
    __syncthreads();

    int lc[4]; int cnt = 0;
#pragma unroll
    for (int q = 0; q < 4; q++) {
        lc[q] = hist[NN - 1 - (tid * 4 + q)];
        cnt += lc[q];
    }
    int base = block_excl_scan_1024(cnt, wsum);
    {
        int run = 0;
#pragma unroll
        for (int q = 0; q < 4; q++) {
            int rbin  = NN - 1 - (tid * 4 + q);
            int above = base + run;
            run += lc[q];
            if (above < KK && above + lc[q] >= KK) { s_t = rbin; s_C = above; }
        }
    }
    __syncthreads();
    const int tbkt = s_t, C = s_C, need = KK - C;

#pragma unroll
    for (int q = 0; q < 4; q++) {
        int i = tid * 4 + q;
        float s = sh[i];
        int bkt = max(0, min(NN - 1, (int)(s * (float)NN)));
        if (bkt == tbkt) {
            int p = atomicAdd(&s_nt, 1);
            if (p < 1024) { tlv[p] = s; tli[p] = i; }
        }
    }
    __syncthreads();
    const int nt = min(s_nt, 1024);

    int kf[4]; int kcnt = 0;
#pragma unroll
    for (int q = 0; q < 4; q++) {
        int i = tid * 4 + q;
        float s = sh[i];
        int bkt = max(0, min(NN - 1, (int)(s * (float)NN)));
        int kept;
        if (bkt > tbkt)      kept = 1;
        else if (bkt < tbkt) kept = 0;
        else {
            int br = 0;
            for (int j = 0; j < nt; j++) {
                float ov = tlv[j]; int oi = tli[j];
                br += (ov > s) || (ov == s && oi < i);
            }
            kept = (br < need);
        }
        kf[q] = kept; kcnt += kept;
    }

    int kbase = block_excl_scan_1024(kcnt, wsum);
    int krun = 0;
#pragma unroll
    for (int q = 0; q < 4; q++) {
        int i = tid * 4 + q;
        float s = sh[i];
        if (kf[q]) {
            int kp = kbase + krun; krun++;
            g_kept_idx[b * KK + kp] = i;
            g_kept_sc [b * KK + kp] = s;
            if (write_out) {
                out_idx[b * KK + kp] = (float)i;
                out_sc [b * KK + kp] = s;
            }
        } else {
            int dp = i - (kbase + krun);
            g_drop_idx[b * MM + dp] = i;
            g_drop_sc [b * MM + dp] = s;
        }
    }
}

// ---------------- K2: gather + normalize + fp16 hi/lo split + init out ----
__global__ void prep_kernel(const float* __restrict__ tok, float* __restrict__ out_tok)
{
    if (blockIdx.x == 0 && threadIdx.x < BB * 8) g_nflag2[threadIdx.x] = 0;

    int w    = (blockIdx.x * blockDim.x + threadIdx.x) >> 5;
    int lane = threadIdx.x & 31;
    if (w >= BB * NN) return;

    if (lane == 0 && w < BB * MM) g_amax[w] = 0ull;

    int b, gi;
    int is_kept;
    __half *dh, *dl;
    const int half_ = BB * KK;
    if (w < half_) {
        b  = w >> 10;
        gi = g_kept_idx[w];
        dh = g_Kh + (size_t)w * DD;
        dl = g_Kl + (size_t)w * DD;
        is_kept = 1;
    } else {
        int w2 = w - half_;
        b  = w2 / MM;
        gi = g_drop_idx[w2];
        dh = g_Dh + (size_t)w2 * DD;
        dl = g_Dl + (size_t)w2 * DD;
        is_kept = 0;
    }

    const float4* src = (const float4*)(tok + ((size_t)b * NN + gi) * DD);
    float4 x[8];
    float ss = 0.f;
#pragma unroll
    for (int i = 0; i < 8; i++) {
        x[i] = src[lane + 32 * i];
        ss += x[i].x * x[i].x + x[i].y * x[i].y + x[i].z * x[i].z + x[i].w * x[i].w;
    }
#pragma unroll
    for (int o = 16; o; o >>= 1) ss += __shfl_xor_sync(0xffffffffu, ss, o);
    float inv = 256.0f / fmaxf(sqrtf(ss), 1e-12f);   // scale lift x256

    if (is_kept) {
        float ksc = fmaxf(g_kept_sc[w], 0.0f);
        float4* dst = (float4*)(out_tok + (size_t)w * DD);
#pragma unroll
        for (int i = 0; i < 8; i++) {
            float4 y = x[i];
            y.x *= ksc; y.y *= ksc; y.z *= ksc; y.w *= ksc;
            dst[lane + 32 * i] = y;
        }
        if (!lane) g_sacc[w] = ksc;
    }

#pragma unroll
    for (int i = 0; i < 8; i++) {
        float v[4] = { x[i].x * inv, x[i].y * inv, x[i].z * inv, x[i].w * inv };
        __half h[4], l[4];
#pragma unroll
        for (int q = 0; q < 4; q++) {
            h[q] = __float2half_rn(v[q]);
            l[q] = __float2half_rn(v[q] - __half2float(h[q]));
        }
        int e = (lane + 32 * i) * 4;
        uint2 hv, lv;
        hv.x = ((uint32_t)__half_as_ushort(h[1]) << 16) | __half_as_ushort(h[0]);
        hv.y = ((uint32_t)__half_as_ushort(h[3]) << 16) | __half_as_ushort(h[2]);
        lv.x = ((uint32_t)__half_as_ushort(l[1]) << 16) | __half_as_ushort(l[0]);
        lv.y = ((uint32_t)__half_as_ushort(l[3]) << 16) | __half_as_ushort(l[2]);
        *(uint2*)(dh + e) = hv;
        *(uint2*)(dl + e) = lv;
    }
}

// ---------------- K3a: coarse 1-term GEMM (Ah*Bh), 128x128 CTA, KC=64 -----
#define KC1 64
#define TILE1 (128 * 128)         // 16384 B per tile (128 rows x 128B)
#define STAGE1 (2 * TILE1)        // 32768 B per stage (Ah, Bh)
#define NST1 3
#define NCH1 (DD / KC1)           // 16

__global__ void __launch_bounds__(256, 2) gemm1_kernel()
{
    extern __shared__ __align__(128) char smem_dyn[];
    const uint32_t sBase = smem_u32(smem_dyn);

    const int b    = blockIdx.z;
    const int m0   = blockIdx.x * 128;
    const int n0   = blockIdx.y * 128;
    const int tid  = threadIdx.x;
    const int lane = tid & 31;
    const int wid  = tid >> 5;
    const int wm   = wid & 3;
    const int wn   = wid >> 2;

    // load mapping: row = tid>>1, 64B half = (tid&1)*4 granules
    const int lrow = tid >> 1;
    const int j0   = (tid & 1) * 4;

    const char* pAh = (const char*)(g_Dh + ((size_t)b * MM + m0 + lrow) * DD) + j0 * 16;
    const char* pBh = (const char*)(g_Kh + ((size_t)b * KK + n0 + lrow) * DD) + j0 * 16;

    float acc[2][8][4];
#pragma unroll
    for (int mi = 0; mi < 2; mi++)
#pragma unroll
        for (int ni = 0; ni < 8; ni++)
#pragma unroll
            for (int j = 0; j < 4; j++) acc[mi][ni][j] = 0.f;

    const int aRow0 = wm * 32 + (lane & 15);
    const int aCb   = (lane >> 4) & 1;
    const int bRow0 = wn * 64 + (lane & 7) + ((lane & 16) ? 8 : 0);
    const int bCb   = (lane >> 3) & 1;

    auto issue = [&](int c, int st) {
        const int off = c * (KC1 * 2);     // 128B along K
        uint32_t dA = sBase + (uint32_t)(st * STAGE1);
        uint32_t dB = dA + TILE1;
#pragma unroll
        for (int k = 0; k < 4; k++) {
            uint32_t o = swz128(lrow, j0 + k);
            cp16cg(dA + o, pAh + off + k * 16);
            cp16ca(dB + o, pBh + off + k * 16);
        }
    };

    issue(0, 0); CP_COMMIT();
    issue(1, 1); CP_COMMIT();

    int buf = 0, nbuf = 2;
    for (int c = 0; c < NCH1; c++) {
        if (c + 1 < NCH1) { CP_WAIT1(); } else { CP_WAIT0(); }
        __syncthreads();
        if (c + 2 < NCH1) {
            issue(c + 2, nbuf);
            CP_COMMIT();
        }

        const uint32_t stA = sBase + (uint32_t)(buf * STAGE1);
        const uint32_t stB = stA + TILE1;

#pragma unroll
        for (int s = 0; s < 4; s++) {
            uint32_t ah[2][4];
#pragma unroll
            for (int mi = 0; mi < 2; mi++)
                ldsm_x4(ah[mi], stA + swz128(aRow0 + mi * 16, s * 2 + aCb));
#pragma unroll
            for (int np = 0; np < 4; np++) {
                uint32_t bh[4];
                ldsm_x4(bh, stB + swz128(bRow0 + np * 16, s * 2 + bCb));
#pragma unroll
                for (int mi = 0; mi < 2; mi++)
#pragma unroll
                    for (int nj = 0; nj < 2; nj++)
                        mma16816h(acc[mi][np * 2 + nj], ah[mi], bh[nj * 2], bh[nj * 2 + 1]);
            }
        }

        buf  = (buf  == NST1 - 1) ? 0 : buf + 1;
        nbuf = (nbuf == NST1 - 1) ? 0 : nbuf + 1;
    }

    // epilogue: per-row top1(val,col)+top2(val) over THIS warp's 64 columns.
    // Slot = (tile, n-half=wn): exactly one writing warp per slot.
#pragma unroll
    for (int mi = 0; mi < 2; mi++) {
#pragma unroll
        for (int h = 0; h < 2; h++) {
            int rowl = wm * 32 + mi * 16 + h * 8 + (lane >> 2);
            float bv = -FLT_MAX; int bc = 0; float t2 = -FLT_MAX;
#pragma unroll
            for (int ni = 0; ni < 8; ni++) {
#pragma unroll
                for (int j = 0; j < 2; j++) {
                    float v = acc[mi][ni][h * 2 + j];
                    int col = n0 + wn * 64 + ni * 8 + (lane & 3) * 2 + j;
                    if (v > bv || (v == bv && col < bc)) { t2 = fmaxf(t2, bv); bv = v; bc = col; }
                    else t2 = fmaxf(t2, v);
                }
            }
#pragma unroll
            for (int m = 1; m < 4; m <<= 1) {
                float ov = __shfl_xor_sync(0xffffffffu, bv, m);
                int   oc = __shfl_xor_sync(0xffffffffu, bc, m);
                float ot = __shfl_xor_sync(0xffffffffu, t2, m);
                if (ov > bv || (ov == bv && oc < bc)) {
                    t2 = fmaxf(t2, bv); bv = ov; bc = oc; t2 = fmaxf(t2, ot);
                } else {
                    t2 = fmaxf(t2, ov); t2 = fmaxf(t2, ot);
                }
            }
            if ((lane & 3) == 0) {
                size_t o16 = ((size_t)(b * MM + m0 + rowl)) * 16 + blockIdx.y * 2 + wn;
                g_t1val[o16] = bv; g_t1col[o16] = bc; g_t2val[o16] = t2;
            }
        }
    }
}

// ---------------- K3b: decide — global THR, candidate-tile lists ----------
__global__ void decide_kernel()
{
    int r = blockIdx.x * 256 + threadIdx.x;
    if (r >= BB * MM) return;
    int b = r / MM;

    float tv[16]; int tc[16]; float t2s[16];
#pragma unroll
    for (int t = 0; t < 16; t++) {
        tv[t]  = g_t1val[(size_t)r * 16 + t];
        tc[t]  = g_t1col[(size_t)r * 16 + t];
        t2s[t] = g_t2val[(size_t)r * 16 + t];
    }

    float v1 = -FLT_MAX; int c1 = 0; float v2 = -FLT_MAX;
#pragma unroll
    for (int t = 0; t < 16; t++) {
        float v = tv[t]; int c = tc[t];
        if (v > v1 || (v == v1 && c < c1)) { v2 = fmaxf(v2, v1); v1 = v; c1 = c; }
        else v2 = fmaxf(v2, v);
        v2 = fmaxf(v2, t2s[t]);
    }

    if (v1 - v2 > THR) {
        g_assign[r] = c1;
    } else {
        g_assign[r] = -1;
        float cut = v1 - TCUT;
#pragma unroll
        for (int t = 0; t < 8; t++) {
            float tmax = fmaxf(tv[2 * t], tv[2 * t + 1]);
            if (tmax >= cut) {
                int p = atomicAdd(&g_nflag2[b * 8 + t], 1);
                g_flag2[(size_t)(b * 8 + t) * MM + p] = r - b * MM;
            }
        }
    }
}

// ---------------- K3c: exact 3-term recheck, per-(batch,tile) row lists ---
#define KC 32
#define NCHUNK (DD / KC)          // 32
#define TILE_SZ (128 * 64)        // 8192 bytes per tile
#define STAGEB (4 * TILE_SZ)      // Ah,Al,Bh,Bl
#define NSTAGE 3

__global__ void __launch_bounds__(256, 2) recheck_kernel()
{
    const int b  = blockIdx.z;
    const int nt = blockIdx.y;
    const int mt = blockIdx.x;
    const int cnt = g_nflag2[b * 8 + nt];
    if (mt * 128 >= cnt) return;

    extern __shared__ __align__(128) char smem_dyn[];
    const uint32_t sBase = smem_u32(smem_dyn);
    __shared__ int s_ridx[128];

    const int n0   = nt * 128;
    const int tid  = threadIdx.x;
    const int lane = tid & 31;
    const int wid  = tid >> 5;
    const int wm   = wid & 3;
    const int wn   = wid >> 2;

    if (tid < 128) {
        int p = mt * 128 + tid;
        if (p >= cnt) p = cnt - 1;
        s_ridx[tid] = g_flag2[(size_t)(b * 8 + nt) * MM + p];
    }
    __syncthreads();

    const int lrow = tid >> 1;
    const int j0   = (tid & 1) * 2;
    const int arow = s_ridx[lrow];

    const char* pAh = (const char*)(g_Dh + ((size_t)b * MM + arow) * DD) + j0 * 16;
    const char* pAl = (const char*)(g_Dl + ((size_t)b * MM + arow) * DD) + j0 * 16;
    const char* pBh = (const char*)(g_Kh + ((size_t)b * KK + n0 + lrow) * DD) + j0 * 16;
    const char* pBl = (const char*)(g_Kl + ((size_t)b * KK + n0 + lrow) * DD) + j0 * 16;
    const uint32_t stDst = sBase + swz(lrow, j0);

    float acc[2][8][4];
#pragma unroll
    for (int mi = 0; mi < 2; mi++)
#pragma unroll
        for (int ni = 0; ni < 8; ni++)
#pragma unroll
            for (int j = 0; j < 4; j++) acc[mi][ni][j] = 0.f;

    const int aRow0 = wm * 32 + (lane & 15);
    const int aCb   = (lane >> 4) & 1;
    const int bRow0 = wn * 64 + (lane & 7) + ((lane & 16) ? 8 : 0);
    const int bCb   = (lane >> 3) & 1;

    auto issue = [&](int c, int st) {
        const int off = c * (KC * 2);
        uint32_t d = stDst + (uint32_t)(st * STAGEB);
        cp16cg(d,                       pAh + off);
        cp16cg(d ^ 16,                  pAh + off + 16);
        cp16cg(d + TILE_SZ,             pAl + off);
        cp16cg((d + TILE_SZ) ^ 16,      pAl + off + 16);
        cp16ca(d + 2 * TILE_SZ,         pBh + off);
        cp16ca((d + 2 * TILE_SZ) ^ 16,  pBh + off + 16);
        cp16ca(d + 3 * TILE_SZ,         pBl + off);
        cp16ca((d + 3 * TILE_SZ) ^ 16,  pBl + off + 16);
    };

    issue(0, 0); CP_COMMIT();
    issue(1, 1); CP_COMMIT();

    int buf = 0, nbuf = 2;
    for (int c = 0; c < NCHUNK; c++) {
        if (c + 1 < NCHUNK) { CP_WAIT1(); } else { CP_WAIT0(); }
        __syncthreads();
        if (c + 2 < NCHUNK) {
            issue(c + 2, nbuf);
            CP_COMMIT();
        }

        const uint32_t stAh = sBase + (uint32_t)(buf * STAGEB);
        const uint32_t stAl = stAh + TILE_SZ;
        const uint32_t stBh = stAh + 2 * TILE_SZ;
        const uint32_t stBl = stAh + 3 * TILE_SZ;

#pragma unroll
        for (int s = 0; s < 2; s++) {
            const int ac = s * 2 + aCb;
            const int bc = s * 2 + bCb;
            uint32_t ah[2][4], al[2][4];
#pragma unroll
            for (int mi = 0; mi < 2; mi++) {
                uint32_t o = swz(aRow0 + mi * 16, ac);
                ldsm_x4(ah[mi], stAh + o);
                ldsm_x4(al[mi], stAl + o);
            }
#pragma unroll
            for (int np = 0; np < 4; np++) {
                uint32_t o = swz(bRow0 + np * 16, bc);
                uint32_t bh[4], bl[4];
                ldsm_x4(bh, stBh + o);
                ldsm_x4(bl, stBl + o);
#pragma unroll
                for (int mi = 0; mi < 2; mi++)
#pragma unroll
                    for (int nj = 0; nj < 2; nj++)
                        mma16816h(acc[mi][np * 2 + nj], ah[mi], bh[nj * 2], bh[nj * 2 + 1]);
#pragma unroll
                for (int mi = 0; mi < 2; mi++)
#pragma unroll
                    for (int nj = 0; nj < 2; nj++)
                        mma16816h(acc[mi][np * 2 + nj], ah[mi], bl[nj * 2], bl[nj * 2 + 1]);
#pragma unroll
                for (int mi = 0; mi < 2; mi++)
#pragma unroll
                    for (int nj = 0; nj < 2; nj++)
                        mma16816h(acc[mi][np * 2 + nj], al[mi], bh[nj * 2], bh[nj * 2 + 1]);
            }
        }

        buf  = (buf  == NSTAGE - 1) ? 0 : buf + 1;
        nbuf = (nbuf == NSTAGE - 1) ? 0 : nbuf + 1;
    }

    // epilogue: per-thread rows -> quad reduce -> global atomicMax (indirected)
#pragma unroll
    for (int mi = 0; mi < 2; mi++) {
#pragma unroll
        for (int h = 0; h < 2; h++) {
            int rowl = wm * 32 + mi * 16 + h * 8 + (lane >> 2);
            float bv = -FLT_MAX; int bc2 = 0;
#pragma unroll
            for (int ni = 0; ni < 8; ni++) {
#pragma unroll
                for (int j = 0; j < 2; j++) {
                    float v = acc[mi][ni][h * 2 + j];
                    int col = n0 + wn * 64 + ni * 8 + (lane & 3) * 2 + j;
                    if (v > bv || (v == bv && col < bc2)) { bv = v; bc2 = col; }
                }
            }
            uint32_t u = __float_as_uint(bv);
            u = (u & 0x80000000u) ? ~u : (u | 0x80000000u);
            unsigned long long key =
                ((unsigned long long)u << 32) | (unsigned long long)(0xFFFFFFFFu - (uint32_t)bc2);
#pragma unroll
            for (int m = 1; m < 4; m <<= 1) {
                unsigned long long o = shfl_xor_u64(key, m);
                if (o > key) key = o;
            }
            if ((lane & 3) == 0)
                atomicMax(&g_amax[b * MM + s_ridx[rowl]], key);
        }
    }
}

// ---------------- K4: scatter-add weighted dropped tokens (vec4 RED) ------
__global__ void scatter_kernel(const float* __restrict__ tok, float* __restrict__ out_tok)
{
    int w    = (blockIdx.x * blockDim.x + threadIdx.x) >> 5;
    int lane = threadIdx.x & 31;
    if (w >= BB * MM) return;
    int b = w / MM;
    int a = g_assign[w];
    if (a < 0) {
        unsigned long long key = g_amax[w];
        a = (int)(0xFFFFFFFFu - (uint32_t)(key & 0xFFFFFFFFull));
    }
    a = max(0, min(KK - 1, a));   // safety clamp
    int gi = g_drop_idx[w];
    float dsc = fmaxf(g_drop_sc[w], 0.0f);
    const float4* src = (const float4*)(tok + ((size_t)b * NN + gi) * DD);
    float* dst = out_tok + ((size_t)b * KK + a) * DD;
#pragma unroll
    for (int i = 0; i < 8; i++) {
        float4 x = src[lane + 32 * i];
        float* p = dst + (lane + 32 * i) * 4;
        asm volatile("red.global.add.v4.f32 [%0], {%1, %2, %3, %4};"
                     :: "l"(p), "f"(x.x * dsc), "f"(x.y * dsc),
                        "f"(x.z * dsc), "f"(x.w * dsc) : "memory");
    }
    if (!lane) atomicAdd(&g_sacc[b * KK + a], dsc);
}

// ---------------- K5: divide by denom ----------------
__global__ void final_kernel(float* __restrict__ out_tok)
{
    int w    = (blockIdx.x * blockDim.x + threadIdx.x) >> 5;
    int lane = threadIdx.x & 31;
    if (w >= BB * KK) return;
    float denom = fmaxf(g_sacc[w], 1e-6f);
    float4* p = (float4*)(out_tok + (size_t)w * DD);
#pragma unroll
    for (int i = 0; i < 8; i++) {
        float4 x = p[lane + 32 * i];
        x.x /= denom; x.y /= denom; x.z /= denom; x.w /= denom;
        p[lane + 32 * i] = x;
    }
}

// ---------------- entry ----------------
extern "C" void kernel_launch(void* const* d_in, const int* in_sizes, int n_in,
                              void* d_out, int out_size)
{
    const float* tok    = (const float*)d_in[0];   // [B,N,D] f32
    const float* scores = (const float*)d_in[1];   // [B,N]   f32
    float* out = (float*)d_out;

    float* out_tok = out;                                   // [B,K,D]
    int write_extra = (out_size >= BB * KK * DD + 2 * BB * KK);
    float* out_idx = out + (size_t)BB * KK * DD;            // [B,K] indices (as float)
    float* out_sc  = out_idx + BB * KK;                     // [B,K] scores

    const int smem1 = NST1 * STAGE1;                        // 98304
    const int smem2 = NSTAGE * STAGEB;                      // 98304
    cudaFuncSetAttribute(gemm1_kernel,
                         cudaFuncAttributeMaxDynamicSharedMemorySize, smem1);
    cudaFuncSetAttribute(recheck_kernel,
                         cudaFuncAttributeMaxDynamicSharedMemorySize, smem2);

    topk_kernel<<<BB, 1024>>>(scores, out_idx, out_sc, write_extra);
    prep_kernel<<<(BB * NN) / 8, 256>>>(tok, out_tok);
    dim3 g(MM / 128, KK / 128, BB);
    gemm1_kernel<<<g, 256, smem1>>>();
    decide_kernel<<<(BB * MM) / 256, 256>>>();
    recheck_kernel<<<g, 256, smem2>>>();
    scatter_kernel<<<(BB * MM) / 8, 256>>>(tok, out_tok);
    final_kernel<<<(BB * KK) / 8, 256>>>(out_tok);
}

// round 16
// speedup vs baseline: 1.0742x; 1.0742x over previous
#include <cuda_runtime.h>
#include <cuda_bf16.h>
#include <cuda_fp16.h>
#include <math.h>
#include <float.h>
#include <stdint.h>

#define BB 16
#define NN 4096
#define DD 1024
#define KK 1024
#define MM (NN - KK)   // 3072

#define THR  132.0f    // safe coarse margin (validated R8/R10/R12/R13: zero flips)
#define TCUT 160.0f    // tile-candidate cut (conservative >= 2E)

// ---------------- device scratch (no allocations allowed) ----------------
__device__ int   g_kept_idx[BB * KK];
__device__ float g_kept_sc [BB * KK];
__device__ int   g_drop_idx[BB * MM];
__device__ float g_drop_sc [BB * MM];
__device__ float g_sacc    [BB * KK];
__device__ unsigned long long g_amax[BB * MM];   // packed (orderfloat<<32 | ~col)
__device__ float g_t1val[(size_t)BB * MM * 16];  // per (row, tile, n-half)
__device__ int   g_t1col[(size_t)BB * MM * 16];
__device__ float g_t2val[(size_t)BB * MM * 16];
__device__ int   g_flag2[(size_t)BB * 8 * MM];   // per-(batch,tile) row lists
__device__ int   g_nflag2[BB * 8];
__device__ int   g_assign[BB * MM];

// fp16 hi/lo split of (normalized * 256) gathered rows
__device__ __align__(16) __half g_Dh[(size_t)BB * MM * DD];
__device__ __align__(16) __half g_Dl[(size_t)BB * MM * DD];
__device__ __align__(16) __half g_Kh[(size_t)BB * KK * DD];
__device__ __align__(16) __half g_Kl[(size_t)BB * KK * DD];

// ---------------- PTX helpers ----------------
__device__ __forceinline__ uint32_t smem_u32(const void* p) {
    uint32_t a;
    asm("{ .reg .u64 t; cvta.to.shared.u64 t, %1; cvt.u32.u64 %0, t; }" : "=r"(a) : "l"(p));
    return a;
}
__device__ __forceinline__ void cp16cg(uint32_t dst, const void* src) {
    asm volatile("cp.async.cg.shared.global [%0], [%1], 16;" :: "r"(dst), "l"(src));
}
__device__ __forceinline__ void cp16ca(uint32_t dst, const void* src) {
    asm volatile("cp.async.ca.shared.global [%0], [%1], 16;" :: "r"(dst), "l"(src));
}
#define CP_COMMIT() asm volatile("cp.async.commit_group;" ::: "memory")
#define CP_WAIT1()  asm volatile("cp.async.wait_group 1;" ::: "memory")
#define CP_WAIT0()  asm volatile("cp.async.wait_group 0;" ::: "memory")

__device__ __forceinline__ void ldsm_x4(uint32_t* r, uint32_t addr) {
    asm volatile("ldmatrix.sync.aligned.m8n8.x4.shared.b16 {%0,%1,%2,%3}, [%4];"
        : "=r"(r[0]), "=r"(r[1]), "=r"(r[2]), "=r"(r[3]) : "r"(addr));
}
__device__ __forceinline__ void mma16816h(float* c, const uint32_t* a, uint32_t b0, uint32_t b1) {
    asm volatile(
        "mma.sync.aligned.m16n8k16.row.col.f32.f16.f16.f32 "
        "{%0,%1,%2,%3}, {%4,%5,%6,%7}, {%8,%9}, {%0,%1,%2,%3};"
        : "+f"(c[0]), "+f"(c[1]), "+f"(c[2]), "+f"(c[3])
        : "r"(a[0]), "r"(a[1]), "r"(a[2]), "r"(a[3]), "r"(b0), "r"(b1));
}
__device__ __forceinline__ unsigned long long shfl_xor_u64(unsigned long long x, int m) {
    uint32_t lo = (uint32_t)x, hi = (uint32_t)(x >> 32);
    lo = __shfl_xor_sync(0xffffffffu, lo, m);
    hi = __shfl_xor_sync(0xffffffffu, hi, m);
    return ((unsigned long long)hi << 32) | lo;
}

// swizzled smem offsets
// 64B rows (recheck tiles): chunk in 16B granules, chunk ^= (row>>1)&3
__device__ __forceinline__ uint32_t swz(int row, int chunk) {
    return (uint32_t)(row * 64 + ((chunk ^ ((row >> 1) & 3)) << 4));
}
// 128B rows (gemm1 tiles): classic SW128, granule chunk ^= row&7
__device__ __forceinline__ uint32_t swz128(int row, int chunk) {
    return (uint32_t)(row * 128 + ((chunk ^ (row & 7)) << 4));
}

// ---------------- block scan helper ----------------
__device__ __forceinline__ int block_excl_scan_1024(int val, int* wsum) {
    int tid = threadIdx.x;
    int lane = tid & 31, w = tid >> 5;
    __syncthreads();
    int v = val;
#pragma unroll
    for (int off = 1; off < 32; off <<= 1) {
        int n = __shfl_up_sync(0xffffffffu, v, off);
        if (lane >= off) v += n;
    }
    if (lane == 31) wsum[w] = v;
    __syncthreads();
    if (w == 0) {
        int s = wsum[lane];
#pragma unroll
        for (int off = 1; off < 32; off <<= 1) {
            int n = __shfl_up_sync(0xffffffffu, s, off);
            if (lane >= off) s += n;
        }
        wsum[lane] = s;
    }
    __syncthreads();
    int base = (w ? wsum[w - 1] : 0);
    return base + v - val;
}

// ---------------- K1: exact top-K select (value desc, index asc ties) ------
__global__ void __launch_bounds__(1024) topk_kernel(const float* __restrict__ scores,
                                                    float* __restrict__ out_idx,
                                                    float* __restrict__ out_sc,
                                                    int write_out)
{
    const int b   = blockIdx.x;
    const int tid = threadIdx.x;

    __shared__ float sh[NN];
    __shared__ int   hist[NN];
    __shared__ float tlv[1024];
    __shared__ int   tli[1024];
    __shared__ int   wsum[32];
    __shared__ int   s_t, s_C, s_nt;

    const float* sc = scores + (size_t)b * NN;
#pragma unroll
    for (int q = 0; q < 4; q++) {
        int i = tid * 4 + q;
        sh[i]   = sc[i];
        hist[i] = 0;
    }
    if (tid == 0) s_nt = 0;
    __syncthreads();

#pragma unroll
    for (int q = 0; q < 4; q++) {
        int i = tid * 4 + q;
        float s = sh[i];
        int bkt = (int)(s * (float)NN);
        bkt = max(0, min(NN - 1, bkt));
        atomicAdd(&hist[bkt], 1);
    }
    __syncthreads();

    int lc[4]; int cnt = 0;
#pragma unroll
    for (int q = 0; q < 4; q++) {
        lc[q] = hist[NN - 1 - (tid * 4 + q)];
        cnt += lc[q];
    }
    int base = block_excl_scan_1024(cnt, wsum);
    {
        int run = 0;
#pragma unroll
        for (int q = 0; q < 4; q++) {
            int rbin  = NN - 1 - (tid * 4 + q);
            int above = base + run;
            run += lc[q];
            if (above < KK && above + lc[q] >= KK) { s_t = rbin; s_C = above; }
        }
    }
    __syncthreads();
    const int tbkt = s_t, C = s_C, need = KK - C;

#pragma unroll
    for (int q = 0; q < 4; q++) {
        int i = tid * 4 + q;
        float s = sh[i];
        int bkt = max(0, min(NN - 1, (int)(s * (float)NN)));
        if (bkt == tbkt) {
            int p = atomicAdd(&s_nt, 1);
            if (p < 1024) { tlv[p] = s; tli[p] = i; }
        }
    }
    __syncthreads();
    const int nt = min(s_nt, 1024);

    int kf[4]; int kcnt = 0;
#pragma unroll
    for (int q = 0; q < 4; q++) {
        int i = tid * 4 + q;
        float s = sh[i];
        int bkt = max(0, min(NN - 1, (int)(s * (float)NN)));
        int kept;
        if (bkt > tbkt)      kept = 1;
        else if (bkt < tbkt) kept = 0;
        else {
            int br = 0;
            for (int j = 0; j < nt; j++) {
                float ov = tlv[j]; int oi = tli[j];
                br += (ov > s) || (ov == s && oi < i);
            }
            kept = (br < need);
        }
        kf[q] = kept; kcnt += kept;
    }

    int kbase = block_excl_scan_1024(kcnt, wsum);
    int krun = 0;
#pragma unroll
    for (int q = 0; q < 4; q++) {
        int i = tid * 4 + q;
        float s = sh[i];
        if (kf[q]) {
            int kp = kbase + krun; krun++;
            g_kept_idx[b * KK + kp] = i;
            g_kept_sc [b * KK + kp] = s;
            if (write_out) {
                out_idx[b * KK + kp] = (float)i;
                out_sc [b * KK + kp] = s;
            }
        } else {
            int dp = i - (kbase + krun);
            g_drop_idx[b * MM + dp] = i;
            g_drop_sc [b * MM + dp] = s;
        }
    }
}

// ---------------- K2: gather + normalize + fp16 hi/lo split + init out ----
__global__ void prep_kernel(const float* __restrict__ tok, float* __restrict__ out_tok)
{
    if (blockIdx.x == 0 && threadIdx.x < BB * 8) g_nflag2[threadIdx.x] = 0;

    int w    = (blockIdx.x * blockDim.x + threadIdx.x) >> 5;
    int lane = threadIdx.x & 31;
    if (w >= BB * NN) return;

    if (lane == 0 && w < BB * MM) g_amax[w] = 0ull;

    int b, gi;
    int is_kept;
    __half *dh, *dl;
    const int half_ = BB * KK;
    if (w < half_) {
        b  = w >> 10;
        gi = g_kept_idx[w];
        dh = g_Kh + (size_t)w * DD;
        dl = g_Kl + (size_t)w * DD;
        is_kept = 1;
    } else {
        int w2 = w - half_;
        b  = w2 / MM;
        gi = g_drop_idx[w2];
        dh = g_Dh + (size_t)w2 * DD;
        dl = g_Dl + (size_t)w2 * DD;
        is_kept = 0;
    }

    const float4* src = (const float4*)(tok + ((size_t)b * NN + gi) * DD);
    float4 x[8];
    float ss = 0.f;
#pragma unroll
    for (int i = 0; i < 8; i++) {
        x[i] = src[lane + 32 * i];
        ss += x[i].x * x[i].x + x[i].y * x[i].y + x[i].z * x[i].z + x[i].w * x[i].w;
    }
#pragma unroll
    for (int o = 16; o; o >>= 1) ss += __shfl_xor_sync(0xffffffffu, ss, o);
    float inv = 256.0f / fmaxf(sqrtf(ss), 1e-12f);   // scale lift x256

    if (is_kept) {
        float ksc = fmaxf(g_kept_sc[w], 0.0f);
        float4* dst = (float4*)(out_tok + (size_t)w * DD);
#pragma unroll
        for (int i = 0; i < 8; i++) {
            float4 y = x[i];
            y.x *= ksc; y.y *= ksc; y.z *= ksc; y.w *= ksc;
            dst[lane + 32 * i] = y;
        }
        if (!lane) g_sacc[w] = ksc;
    }

#pragma unroll
    for (int i = 0; i < 8; i++) {
        float v[4] = { x[i].x * inv, x[i].y * inv, x[i].z * inv, x[i].w * inv };
        __half h[4], l[4];
#pragma unroll
        for (int q = 0; q < 4; q++) {
            h[q] = __float2half_rn(v[q]);
            l[q] = __float2half_rn(v[q] - __half2float(h[q]));
        }
        int e = (lane + 32 * i) * 4;
        *(__half2*)(dh + e)     = __half2(h[0], h[1]);
        *(__half2*)(dh + e + 2) = __half2(h[2], h[3]);
        *(__half2*)(dl + e)     = __half2(l[0], l[1]);
        *(__half2*)(dl + e + 2) = __half2(l[2], l[3]);
    }
}

// ---------------- K3a: coarse 1-term GEMM (Ah*Bh), KC=64, SW128 tiles -----
#define KC1 64
#define TILE1 (128 * 128)         // 16384 B per tile (128 rows x 128B)
#define STAGE1 (2 * TILE1)        // 32768 B per stage (Ah, Bh)
#define NST1 3
#define NCH1 (DD / KC1)           // 16

__global__ void __launch_bounds__(256, 2) gemm1_kernel()
{
    extern __shared__ __align__(128) char smem_dyn[];
    const uint32_t sBase = smem_u32(smem_dyn);

    const int b    = blockIdx.z;
    const int m0   = blockIdx.x * 128;
    const int n0   = blockIdx.y * 128;
    const int tid  = threadIdx.x;
    const int lane = tid & 31;
    const int wid  = tid >> 5;
    const int wm   = wid & 3;
    const int wn   = wid >> 2;

    // load mapping: row = tid>>1, 64B half = (tid&1)*4 granules
    const int lrow = tid >> 1;
    const int j0   = (tid & 1) * 4;

    const char* pAh = (const char*)(g_Dh + ((size_t)b * MM + m0 + lrow) * DD) + j0 * 16;
    const char* pBh = (const char*)(g_Kh + ((size_t)b * KK + n0 + lrow) * DD) + j0 * 16;

    float acc[2][8][4];
#pragma unroll
    for (int mi = 0; mi < 2; mi++)
#pragma unroll
        for (int ni = 0; ni < 8; ni++)
#pragma unroll
            for (int j = 0; j < 4; j++) acc[mi][ni][j] = 0.f;

    const int aRow0 = wm * 32 + (lane & 15);
    const int aCb   = (lane >> 4) & 1;
    const int bRow0 = wn * 64 + (lane & 7) + ((lane & 16) ? 8 : 0);
    const int bCb   = (lane >> 3) & 1;

    auto issue = [&](int c, int st) {
        const int off = c * (KC1 * 2);     // 128B along K
        uint32_t dA = sBase + (uint32_t)(st * STAGE1);
        uint32_t dB = dA + TILE1;
#pragma unroll
        for (int k = 0; k < 4; k++) {
            uint32_t o = swz128(lrow, j0 + k);
            cp16cg(dA + o, pAh + off + k * 16);
            cp16ca(dB + o, pBh + off + k * 16);
        }
    };

    issue(0, 0); CP_COMMIT();
    issue(1, 1); CP_COMMIT();

    int buf = 0, nbuf = 2;
    for (int c = 0; c < NCH1; c++) {
        if (c + 1 < NCH1) { CP_WAIT1(); } else { CP_WAIT0(); }
        __syncthreads();
        if (c + 2 < NCH1) {
            issue(c + 2, nbuf);
            CP_COMMIT();
        }

        const uint32_t stA = sBase + (uint32_t)(buf * STAGE1);
        const uint32_t stB = stA + TILE1;

#pragma unroll
        for (int s = 0; s < 4; s++) {
            uint32_t ah[2][4];
#pragma unroll
            for (int mi = 0; mi < 2; mi++)
                ldsm_x4(ah[mi], stA + swz128(aRow0 + mi * 16, s * 2 + aCb));
#pragma unroll
            for (int np = 0; np < 4; np++) {
                uint32_t bh[4];
                ldsm_x4(bh, stB + swz128(bRow0 + np * 16, s * 2 + bCb));
#pragma unroll
                for (int mi = 0; mi < 2; mi++)
#pragma unroll
                    for (int nj = 0; nj < 2; nj++)
                        mma16816h(acc[mi][np * 2 + nj], ah[mi], bh[nj * 2], bh[nj * 2 + 1]);
            }
        }

        buf  = (buf  == NST1 - 1) ? 0 : buf + 1;
        nbuf = (nbuf == NST1 - 1) ? 0 : nbuf + 1;
    }

    // epilogue: per-row top1(val,col)+top2(val) over THIS warp's 64 columns.
    // Slot = (tile, n-half=wn): exactly one writing warp per slot.
#pragma unroll
    for (int mi = 0; mi < 2; mi++) {
#pragma unroll
        for (int h = 0; h < 2; h++) {
            int rowl = wm * 32 + mi * 16 + h * 8 + (lane >> 2);
            float bv = -FLT_MAX; int bc = 0; float t2 = -FLT_MAX;
#pragma unroll
            for (int ni = 0; ni < 8; ni++) {
#pragma unroll
                for (int j = 0; j < 2; j++) {
                    float v = acc[mi][ni][h * 2 + j];
                    int col = n0 + wn * 64 + ni * 8 + (lane & 3) * 2 + j;
                    if (v > bv || (v == bv && col < bc)) { t2 = fmaxf(t2, bv); bv = v; bc = col; }
                    else t2 = fmaxf(t2, v);
                }
            }
#pragma unroll
            for (int m = 1; m < 4; m <<= 1) {
                float ov = __shfl_xor_sync(0xffffffffu, bv, m);
                int   oc = __shfl_xor_sync(0xffffffffu, bc, m);
                float ot = __shfl_xor_sync(0xffffffffu, t2, m);
                if (ov > bv || (ov == bv && oc < bc)) {
                    t2 = fmaxf(t2, bv); bv = ov; bc = oc; t2 = fmaxf(t2, ot);
                } else {
                    t2 = fmaxf(t2, ov); t2 = fmaxf(t2, ot);
                }
            }
            if ((lane & 3) == 0) {
                size_t o16 = ((size_t)(b * MM + m0 + rowl)) * 16 + blockIdx.y * 2 + wn;
                g_t1val[o16] = bv; g_t1col[o16] = bc; g_t2val[o16] = t2;
            }
        }
    }
}

// ---------------- K3b: decide — global THR, candidate-tile lists ----------
__global__ void decide_kernel()
{
    int r = blockIdx.x * 256 + threadIdx.x;
    if (r >= BB * MM) return;
    int b = r / MM;

    float tv[16]; int tc[16]; float t2s[16];
#pragma unroll
    for (int t = 0; t < 16; t++) {
        tv[t]  = g_t1val[(size_t)r * 16 + t];
        tc[t]  = g_t1col[(size_t)r * 16 + t];
        t2s[t] = g_t2val[(size_t)r * 16 + t];
    }

    float v1 = -FLT_MAX; int c1 = 0; float v2 = -FLT_MAX;
#pragma unroll
    for (int t = 0; t < 16; t++) {
        float v = tv[t]; int c = tc[t];
        if (v > v1 || (v == v1 && c < c1)) { v2 = fmaxf(v2, v1); v1 = v; c1 = c; }
        else v2 = fmaxf(v2, v);
        v2 = fmaxf(v2, t2s[t]);
    }

    if (v1 - v2 > THR) {
        g_assign[r] = c1;
    } else {
        g_assign[r] = -1;
        float cut = v1 - TCUT;
#pragma unroll
        for (int t = 0; t < 8; t++) {
            float tmax = fmaxf(tv[2 * t], tv[2 * t + 1]);
            if (tmax >= cut) {
                int p = atomicAdd(&g_nflag2[b * 8 + t], 1);
                g_flag2[(size_t)(b * 8 + t) * MM + p] = r - b * MM;
            }
        }
    }
}

// ---------------- K3c: exact 3-term recheck, per-(batch,tile) row lists ---
#define KC 32
#define NCHUNK (DD / KC)          // 32
#define TILE_SZ (128 * 64)        // 8192 bytes per tile
#define STAGEB (4 * TILE_SZ)      // Ah,Al,Bh,Bl
#define NSTAGE 3

__global__ void __launch_bounds__(256, 2) recheck_kernel()
{
    const int b  = blockIdx.z;
    const int nt = blockIdx.y;
    const int mt = blockIdx.x;
    const int cnt = g_nflag2[b * 8 + nt];
    if (mt * 128 >= cnt) return;

    extern __shared__ __align__(128) char smem_dyn[];
    const uint32_t sBase = smem_u32(smem_dyn);
    __shared__ int s_ridx[128];

    const int n0   = nt * 128;
    const int tid  = threadIdx.x;
    const int lane = tid & 31;
    const int wid  = tid >> 5;
    const int wm   = wid & 3;
    const int wn   = wid >> 2;

    if (tid < 128) {
        int p = mt * 128 + tid;
        if (p >= cnt) p = cnt - 1;
        s_ridx[tid] = g_flag2[(size_t)(b * 8 + nt) * MM + p];
    }
    __syncthreads();

    const int lrow = tid >> 1;
    const int j0   = (tid & 1) * 2;
    const int arow = s_ridx[lrow];

    const char* pAh = (const char*)(g_Dh + ((size_t)b * MM + arow) * DD) + j0 * 16;
    const char* pAl = (const char*)(g_Dl + ((size_t)b * MM + arow) * DD) + j0 * 16;
    const char* pBh = (const char*)(g_Kh + ((size_t)b * KK + n0 + lrow) * DD) + j0 * 16;
    const char* pBl = (const char*)(g_Kl + ((size_t)b * KK + n0 + lrow) * DD) + j0 * 16;
    const uint32_t stDst = sBase + swz(lrow, j0);

    float acc[2][8][4];
#pragma unroll
    for (int mi = 0; mi < 2; mi++)
#pragma unroll
        for (int ni = 0; ni < 8; ni++)
#pragma unroll
            for (int j = 0; j < 4; j++) acc[mi][ni][j] = 0.f;

    const int aRow0 = wm * 32 + (lane & 15);
    const int aCb   = (lane >> 4) & 1;
    const int bRow0 = wn * 64 + (lane & 7) + ((lane & 16) ? 8 : 0);
    const int bCb   = (lane >> 3) & 1;

    auto issue = [&](int c, int st) {
        const int off = c * (KC * 2);
        uint32_t d = stDst + (uint32_t)(st * STAGEB);
        cp16cg(d,                       pAh + off);
        cp16cg(d ^ 16,                  pAh + off + 16);
        cp16cg(d + TILE_SZ,             pAl + off);
        cp16cg((d + TILE_SZ) ^ 16,      pAl + off + 16);
        cp16ca(d + 2 * TILE_SZ,         pBh + off);
        cp16ca((d + 2 * TILE_SZ) ^ 16,  pBh + off + 16);
        cp16ca(d + 3 * TILE_SZ,         pBl + off);
        cp16ca((d + 3 * TILE_SZ) ^ 16,  pBl + off + 16);
    };

    issue(0, 0); CP_COMMIT();
    issue(1, 1); CP_COMMIT();

    int buf = 0, nbuf = 2;
    for (int c = 0; c < NCHUNK; c++) {
        if (c + 1 < NCHUNK) { CP_WAIT1(); } else { CP_WAIT0(); }
        __syncthreads();
        if (c + 2 < NCHUNK) {
            issue(c + 2, nbuf);
            CP_COMMIT();
        }

        const uint32_t stAh = sBase + (uint32_t)(buf * STAGEB);
        const uint32_t stAl = stAh + TILE_SZ;
        const uint32_t stBh = stAh + 2 * TILE_SZ;
        const uint32_t stBl = stAh + 3 * TILE_SZ;

#pragma unroll
        for (int s = 0; s < 2; s++) {
            const int ac = s * 2 + aCb;
            const int bc = s * 2 + bCb;
            uint32_t ah[2][4], al[2][4];
#pragma unroll
            for (int mi = 0; mi < 2; mi++) {
                uint32_t o = swz(aRow0 + mi * 16, ac);
                ldsm_x4(ah[mi], stAh + o);
                ldsm_x4(al[mi], stAl + o);
            }
#pragma unroll
            for (int np = 0; np < 4; np++) {
                uint32_t o = swz(bRow0 + np * 16, bc);
                uint32_t bh[4], bl[4];
                ldsm_x4(bh, stBh + o);
                ldsm_x4(bl, stBl + o);
#pragma unroll
                for (int mi = 0; mi < 2; mi++)
#pragma unroll
                    for (int nj = 0; nj < 2; nj++)
                        mma16816h(acc[mi][np * 2 + nj], ah[mi], bh[nj * 2], bh[nj * 2 + 1]);
#pragma unroll
                for (int mi = 0; mi < 2; mi++)
#pragma unroll
                    for (int nj = 0; nj < 2; nj++)
                        mma16816h(acc[mi][np * 2 + nj], ah[mi], bl[nj * 2], bl[nj * 2 + 1]);
#pragma unroll
                for (int mi = 0; mi < 2; mi++)
#pragma unroll
                    for (int nj = 0; nj < 2; nj++)
                        mma16816h(acc[mi][np * 2 + nj], al[mi], bh[nj * 2], bh[nj * 2 + 1]);
            }
        }

        buf  = (buf  == NSTAGE - 1) ? 0 : buf + 1;
        nbuf = (nbuf == NSTAGE - 1) ? 0 : nbuf + 1;
    }

    // epilogue: per-thread rows -> quad reduce -> global atomicMax (indirected)
#pragma unroll
    for (int mi = 0; mi < 2; mi++) {
#pragma unroll
        for (int h = 0; h < 2; h++) {
            int rowl = wm * 32 + mi * 16 + h * 8 + (lane >> 2);
            float bv = -FLT_MAX; int bc2 = 0;
#pragma unroll
            for (int ni = 0; ni < 8; ni++) {
#pragma unroll
                for (int j = 0; j < 2; j++) {
                    float v = acc[mi][ni][h * 2 + j];
                    int col = n0 + wn * 64 + ni * 8 + (lane & 3) * 2 + j;
                    if (v > bv || (v == bv && col < bc2)) { bv = v; bc2 = col; }
                }
            }
            uint32_t u = __float_as_uint(bv);
            u = (u & 0x80000000u) ? ~u : (u | 0x80000000u);
            unsigned long long key =
                ((unsigned long long)u << 32) | (unsigned long long)(0xFFFFFFFFu - (uint32_t)bc2);
#pragma unroll
            for (int m = 1; m < 4; m <<= 1) {
                unsigned long long o = shfl_xor_u64(key, m);
                if (o > key) key = o;
            }
            if ((lane & 3) == 0)
                atomicMax(&g_amax[b * MM + s_ridx[rowl]], key);
        }
    }
}

// ---------------- K4: scatter-add weighted dropped tokens (vec4 RED) ------
__global__ void scatter_kernel(const float* __restrict__ tok, float* __restrict__ out_tok)
{
    int w    = (blockIdx.x * blockDim.x + threadIdx.x) >> 5;
    int lane = threadIdx.x & 31;
    if (w >= BB * MM) return;
    int b = w / MM;
    int a = g_assign[w];
    if (a < 0) {
        unsigned long long key = g_amax[w];
        a = (int)(0xFFFFFFFFu - (uint32_t)(key & 0xFFFFFFFFull));
    }
    a = max(0, min(KK - 1, a));   // safety clamp
    int gi = g_drop_idx[w];
    float dsc = fmaxf(g_drop_sc[w], 0.0f);
    const float4* src = (const float4*)(tok + ((size_t)b * NN + gi) * DD);
    float* dst = out_tok + ((size_t)b * KK + a) * DD;
#pragma unroll
    for (int i = 0; i < 8; i++) {
        float4 x = src[lane + 32 * i];
        float* p = dst + (lane + 32 * i) * 4;
        asm volatile("red.global.add.v4.f32 [%0], {%1, %2, %3, %4};"
                     :: "l"(p), "f"(x.x * dsc), "f"(x.y * dsc),
                        "f"(x.z * dsc), "f"(x.w * dsc) : "memory");
    }
    if (!lane) atomicAdd(&g_sacc[b * KK + a], dsc);
}

// ---------------- K5: divide by denom ----------------
__global__ void final_kernel(float* __restrict__ out_tok)
{
    int w    = (blockIdx.x * blockDim.x + threadIdx.x) >> 5;
    int lane = threadIdx.x & 31;
    if (w >= BB * KK) return;
    float denom = fmaxf(g_sacc[w], 1e-6f);
    float4* p = (float4*)(out_tok + (size_t)w * DD);
#pragma unroll
    for (int i = 0; i < 8; i++) {
        float4 x = p[lane + 32 * i];
        x.x /= denom; x.y /= denom; x.z /= denom; x.w /= denom;
        p[lane + 32 * i] = x;
    }
}

// ---------------- entry ----------------
extern "C" void kernel_launch(void* const* d_in, const int* in_sizes, int n_in,
                              void* d_out, int out_size)
{
    const float* tok    = (const float*)d_in[0];   // [B,N,D] f32
    const float* scores = (const float*)d_in[1];   // [B,N]   f32
    float* out = (float*)d_out;

    float* out_tok = out;                                   // [B,K,D]
    int write_extra = (out_size >= BB * KK * DD + 2 * BB * KK);
    float* out_idx = out + (size_t)BB * KK * DD;            // [B,K] indices (as float)
    float* out_sc  = out_idx + BB * KK;                     // [B,K] scores

    const int smem1 = NST1 * STAGE1;                        // 98304
    const int smem2 = NSTAGE * STAGEB;                      // 98304
    cudaFuncSetAttribute(gemm1_kernel,
                         cudaFuncAttributeMaxDynamicSharedMemorySize, smem1);
    cudaFuncSetAttribute(recheck_kernel,
                         cudaFuncAttributeMaxDynamicSharedMemorySize, smem2);

    topk_kernel<<<BB, 1024>>>(scores, out_idx, out_sc, write_extra);
    prep_kernel<<<(BB * NN) / 8, 256>>>(tok, out_tok);
    dim3 g(MM / 128, KK / 128, BB);
    gemm1_kernel<<<g, 256, smem1>>>();
    decide_kernel<<<(BB * MM) / 256, 256>>>();
    recheck_kernel<<<g, 256, smem2>>>();
    scatter_kernel<<<(BB * MM) / 8, 256>>>(tok, out_tok);
    final_kernel<<<(BB * KK) / 8, 256>>>(out_tok);
}